// round 13
// baseline (speedup 1.0000x reference)
#include <cuda_runtime.h>
#include <cuda_fp16.h>
#include <cstdint>

#define BATCH 2
#define SEQ   2048
#define HID   2048
#define NH    32
#define NG    8
#define HD    64
#define KVD   (NG*HD)     // 512
#define MTOT  (BATCH*SEQ) // 4096
#define NC    (HID + 2*KVD)  // 3072 combined QKV cols

typedef __half fp16;

// ---------------- device scratch (no allocation allowed) ----------------
__device__ fp16 g_xh[(size_t)MTOT*HID];                           // hi only
__device__ fp16 g_wch[(size_t)HID*NC];                            // [K, Q|K|V] hi only
__device__ fp16 g_woh[(size_t)HID*HID];                           // [K,N] hi only
__device__ fp16 g_qh[(size_t)BATCH*NH*SEQ*HD];                    // hi only
__device__ fp16 g_kh[(size_t)BATCH*NG*SEQ*HD];                    // hi only
__device__ fp16 g_vh[(size_t)BATCH*NG*HD*SEQ];                    // [b,g,d,s] hi only
__device__ fp16 g_oh[(size_t)MTOT*HID];                           // hi only

// ---------------- helpers ----------------
__device__ __forceinline__ uint32_t pack2h(float x0, float x1) {
    __half2 hb = __floats2half2_rn(x0, x1);
    return *reinterpret_cast<uint32_t*>(&hb);
}

__device__ __forceinline__ void mma_f16(float d[4], const uint32_t a[4],
                                        uint32_t b0, uint32_t b1) {
    asm volatile(
        "mma.sync.aligned.m16n8k16.row.col.f32.f16.f16.f32 "
        "{%0,%1,%2,%3}, {%4,%5,%6,%7}, {%8,%9}, {%0,%1,%2,%3};\n"
        : "+f"(d[0]), "+f"(d[1]), "+f"(d[2]), "+f"(d[3])
        : "r"(a[0]), "r"(a[1]), "r"(a[2]), "r"(a[3]), "r"(b0), "r"(b1));
}

__device__ __forceinline__ void ldsm4(uint32_t& r0, uint32_t& r1, uint32_t& r2,
                                      uint32_t& r3, uint32_t addr) {
    asm volatile("ldmatrix.sync.aligned.m8n8.x4.shared.b16 {%0,%1,%2,%3}, [%4];"
                 : "=r"(r0), "=r"(r1), "=r"(r2), "=r"(r3) : "r"(addr));
}
__device__ __forceinline__ void ldsm4t(uint32_t& r0, uint32_t& r1, uint32_t& r2,
                                       uint32_t& r3, uint32_t addr) {
    asm volatile("ldmatrix.sync.aligned.m8n8.x4.trans.shared.b16 {%0,%1,%2,%3}, [%4];"
                 : "=r"(r0), "=r"(r1), "=r"(r2), "=r"(r3) : "r"(addr));
}

__device__ __forceinline__ void cp16(uint32_t saddr, const void* gaddr) {
    asm volatile("cp.async.cg.shared.global [%0], [%1], 16;"
                 :: "r"(saddr), "l"(gaddr) : "memory");
}
#define CP_COMMIT() asm volatile("cp.async.commit_group;" ::: "memory")
#define CP_WAIT0()  asm volatile("cp.async.wait_group 0;"  ::: "memory")

// exp2 on a packed half2 (one MUFU op for two values)
__device__ __forceinline__ uint32_t h2ex2(uint32_t x) {
    uint32_t r;
    asm("ex2.approx.f16x2 %0, %1;" : "=r"(r) : "r"(x));
    return r;
}

// ---------------- fused fp32 -> fp16 convert (X, Wq|Wk|Wv combined, Wo) ---
#define XF4  ((MTOT*HID)/4)       // 2097152
#define WQF4 ((HID*HID)/4)        // 1048576
#define WKF4 ((HID*KVD)/4)        // 262144
#define ALLF4 (XF4 + WQF4 + 2*WKF4 + WQF4)

__global__ __launch_bounds__(256) void convert_all_kernel(
    const float* __restrict__ X,  const float* __restrict__ Wq,
    const float* __restrict__ Wk, const float* __restrict__ Wv,
    const float* __restrict__ Wo,
    fp16* __restrict__ xh, fp16* __restrict__ wch, fp16* __restrict__ woh)
{
    const int i = blockIdx.x * blockDim.x + threadIdx.x;
    if (i >= ALLF4) return;

    if (i < XF4) {
        float4 v = reinterpret_cast<const float4*>(X)[i];
        reinterpret_cast<uint32_t*>(xh)[i * 2]     = pack2h(v.x, v.y);
        reinterpret_cast<uint32_t*>(xh)[i * 2 + 1] = pack2h(v.z, v.w);
        return;
    }
    int j = i - XF4;
    const float* src;
    int Nsrc, colOff;
    if (j < WQF4)                { src = Wq; Nsrc = HID; colOff = 0; }
    else if (j < WQF4 + WKF4)    { src = Wk; Nsrc = KVD; colOff = HID;       j -= WQF4; }
    else if (j < WQF4 + 2*WKF4)  { src = Wv; Nsrc = KVD; colOff = HID + KVD; j -= WQF4 + WKF4; }
    else {                       // Wo -> woh linear
        j -= WQF4 + 2 * WKF4;
        float4 v = reinterpret_cast<const float4*>(Wo)[j];
        reinterpret_cast<uint32_t*>(woh)[j * 2]     = pack2h(v.x, v.y);
        reinterpret_cast<uint32_t*>(woh)[j * 2 + 1] = pack2h(v.z, v.w);
        return;
    }
    const int perRow = Nsrc >> 2;
    const int k = j / perRow;
    const int c4 = (j - k * perRow) * 4;
    float4 v = reinterpret_cast<const float4*>(src)[j];
    const size_t o = ((size_t)k * NC + colOff + c4) >> 1;
    reinterpret_cast<uint32_t*>(wch)[o]     = pack2h(v.x, v.y);
    reinterpret_cast<uint32_t*>(wch)[o + 1] = pack2h(v.z, v.w);
}

// ---------------------------------------------------------------------------
// 1-term fp16 GEMM: C = Ah @ Bh + bias. CTA 128x128, BK=64, 256 threads
// (8 warps 4x2, warp tile 32x64), cp.async double buffer + ldmatrix.
// MODE 0: fp32 +bias -> Cf (O projection)
// MODE 4: combined QKV epilogue: Q -> hi [b,h,s,d]; K -> hi [b,g,s,d]
//         scaled by 0.125*log2e; V -> hi transposed [b,g,d,s]
// ---------------------------------------------------------------------------
#define GAP 72     // A smem pitch (fp16): 64 k + 8 pad
#define GBP 136    // B smem pitch (fp16): 128 n + 8 pad
#define GA_BYTES (128 * GAP * 2)            // 18432
#define GB_BYTES (64 * GBP * 2)             // 17408
#define GSTAGE   (GA_BYTES + GB_BYTES)      // 35840
#define GEMM_SMEM (2 * GSTAGE)              // 71680
#define KSCALE (0.125f * 1.44269504088896f)

template<int MODE>
__global__ __launch_bounds__(256, 2) void gemm_kernel(
    const fp16* __restrict__ Ah, const fp16* __restrict__ Bh,
    const float* __restrict__ bias0, const float* __restrict__ bias1,
    const float* __restrict__ bias2,
    float* __restrict__ Cf, int M, int N, int K)
{
    extern __shared__ char smc[];
    const uint32_t sbase = (uint32_t)__cvta_generic_to_shared(smc);

    const int tid  = threadIdx.x;
    const int lane = tid & 31;
    const int wid  = tid >> 5;
    const int g = lane >> 2, c = lane & 3;
    const int quad = lane >> 3, r8 = lane & 7;
    const int wm0 = (wid & 3) * 32;
    const int wn0 = (wid >> 2) * 64;
    const int row0 = blockIdx.y * 128;
    const int col0 = blockIdx.x * 128;

    float acc[2][8][4];
    #pragma unroll
    for (int mt = 0; mt < 2; mt++)
        #pragma unroll
        for (int nt = 0; nt < 8; nt++)
            #pragma unroll
            for (int j = 0; j < 4; j++) acc[mt][nt][j] = 0.0f;

    const int NT = K / 64;

    auto fill = [&](int kt, int st) {
        const int k0 = kt * 64;
        const uint32_t s0 = sbase + st * GSTAGE;
        // A: 128 rows x 64 k (1024 f4, 4 per thread)
        #pragma unroll
        for (int i = 0; i < 4; i++) {
            const int idx = tid + i * 256;
            const int r = idx >> 3, q = (idx & 7) * 8;
            const size_t go = (size_t)(row0 + r) * K + k0 + q;
            cp16(s0 + (r * GAP + q) * 2, Ah + go);
        }
        // B: 64 k-rows x 128 n (1024 f4, 4 per thread)
        #pragma unroll
        for (int i = 0; i < 4; i++) {
            const int idx = tid + i * 256;
            const int r = idx >> 4, q = (idx & 15) * 8;
            const size_t go = (size_t)(k0 + r) * N + col0 + q;
            cp16(s0 + GA_BYTES + (r * GBP + q) * 2, Bh + go);
        }
    };

    fill(0, 0); CP_COMMIT();

    const int arow = (quad & 1) * 8 + r8;
    const int acol = (quad >> 1) * 8;

    for (int kt = 0; kt < NT; kt++) {
        CP_WAIT0();
        __syncthreads();
        if (kt + 1 < NT) { fill(kt + 1, (kt + 1) & 1); CP_COMMIT(); }
        const uint32_t s0 = sbase + (kt & 1) * GSTAGE;

        #pragma unroll
        for (int kk = 0; kk < 4; kk++) {
            uint32_t ah[2][4];
            #pragma unroll
            for (int mt = 0; mt < 2; mt++) {
                const uint32_t aaddr =
                    s0 + ((wm0 + mt * 16 + arow) * GAP + kk * 16 + acol) * 2;
                ldsm4(ah[mt][0], ah[mt][1], ah[mt][2], ah[mt][3], aaddr);
            }
            #pragma unroll
            for (int np = 0; np < 4; np++) {
                const uint32_t baddr = s0 + GA_BYTES +
                    ((kk * 16 + arow) * GBP + wn0 + np * 16 + acol) * 2;
                uint32_t bh0, bh1, bh2, bh3;
                ldsm4t(bh0, bh1, bh2, bh3, baddr);
                #pragma unroll
                for (int mt = 0; mt < 2; mt++) {
                    mma_f16(acc[mt][2*np],   ah[mt], bh0, bh1);
                    mma_f16(acc[mt][2*np+1], ah[mt], bh2, bh3);
                }
            }
        }
    }

    // ---- epilogue ----
    #pragma unroll
    for (int mt = 0; mt < 2; mt++) {
        const int r = row0 + wm0 + mt * 16 + g;     // and r+8
        const int b0 = r >> 11, s0i = r & 2047;
        const int b1 = (r + 8) >> 11, s1i = (r + 8) & 2047;
        #pragma unroll
        for (int nt = 0; nt < 8; nt++) {
            const int n = col0 + wn0 + nt * 8 + 2 * c;
            if (MODE == 0) {
                const float bv0 = bias0[n], bv1 = bias0[n + 1];
                const float v0 = acc[mt][nt][0] + bv0;
                const float v1 = acc[mt][nt][1] + bv1;
                const float v2 = acc[mt][nt][2] + bv0;
                const float v3 = acc[mt][nt][3] + bv1;
                *(float2*)(Cf + (size_t)r * N + n)       = make_float2(v0, v1);
                *(float2*)(Cf + (size_t)(r + 8) * N + n) = make_float2(v2, v3);
            } else {
                if (n < HID) {               // ---- Q: hi [b,h,s,d] ----
                    const float bv0 = bias0[n], bv1 = bias0[n + 1];
                    const int hh = n >> 6, d = n & 63;
                    size_t o0 = (((size_t)(b0 * NH + hh)) * SEQ + s0i) * HD + d;
                    size_t o1 = (((size_t)(b1 * NH + hh)) * SEQ + s1i) * HD + d;
                    *reinterpret_cast<uint32_t*>(g_qh + o0) =
                        pack2h(acc[mt][nt][0] + bv0, acc[mt][nt][1] + bv1);
                    *reinterpret_cast<uint32_t*>(g_qh + o1) =
                        pack2h(acc[mt][nt][2] + bv0, acc[mt][nt][3] + bv1);
                } else if (n < HID + KVD) {  // ---- K: hi [b,g,s,d], xKSCALE ----
                    const int nn = n - HID;
                    const float bv0 = bias1[nn], bv1 = bias1[nn + 1];
                    const float v0 = (acc[mt][nt][0] + bv0) * KSCALE;
                    const float v1 = (acc[mt][nt][1] + bv1) * KSCALE;
                    const float v2 = (acc[mt][nt][2] + bv0) * KSCALE;
                    const float v3 = (acc[mt][nt][3] + bv1) * KSCALE;
                    const int gg = nn >> 6, d = nn & 63;
                    size_t o0 = (((size_t)(b0 * NG + gg)) * SEQ + s0i) * HD + d;
                    size_t o1 = (((size_t)(b1 * NG + gg)) * SEQ + s1i) * HD + d;
                    *reinterpret_cast<uint32_t*>(g_kh + o0) = pack2h(v0, v1);
                    *reinterpret_cast<uint32_t*>(g_kh + o1) = pack2h(v2, v3);
                } else {                     // ---- V: hi transposed [b,g,d,s] ----
                    const int nn = n - HID - KVD;
                    const float bv0 = bias2[nn], bv1 = bias2[nn + 1];
                    const float vals[4] = {
                        acc[mt][nt][0] + bv0, acc[mt][nt][1] + bv1,
                        acc[mt][nt][2] + bv0, acc[mt][nt][3] + bv1 };
                    const int gg = nn >> 6, d = nn & 63;
                    const size_t base0 = ((size_t)(b0 * NG + gg)) * HD;
                    const size_t base1 = ((size_t)(b1 * NG + gg)) * HD;
                    const size_t offs[4] = {
                        (base0 + d) * SEQ + s0i, (base0 + d + 1) * SEQ + s0i,
                        (base1 + d) * SEQ + s1i, (base1 + d + 1) * SEQ + s1i };
                    #pragma unroll
                    for (int j = 0; j < 4; j++)
                        g_vh[offs[j]] = __float2half_rn(vals[j]);
                }
            }
        }
    }
}

// ---------------------------------------------------------------------------
// Flash attention: 1-term fp16 QK + 1-term PV, K/V hi-only in smem,
// ex2.approx.f16x2 softmax (one MUFU per score pair; output IS the P frag;
// approx bias cancels between softmax numerator and denominator).
// Block = (b, h, 128-query tile), 256 threads.
// ---------------------------------------------------------------------------
#define AKP 72
#define AK_BYTES (64 * AKP * 2)        // 9216
#define ASTAGE   (2 * AK_BYTES)        // 18432
#define ATTN_SMEM (2 * ASTAGE)         // 36864

__global__ __launch_bounds__(256, 2) void attn_kernel(
    const fp16* __restrict__ Qh, const fp16* __restrict__ Kh,
    const fp16* __restrict__ Vh, fp16* __restrict__ Oh)
{
    extern __shared__ char smc[];
    const uint32_t sbase = (uint32_t)__cvta_generic_to_shared(smc);

    const int tid  = threadIdx.x;
    const int lane = tid & 31;
    const int wid  = tid >> 5;
    const int g = lane >> 2, c = lane & 3;
    const int quad = lane >> 3, r8 = lane & 7;
    const int wr0 = wid * 16;
    const int lrow = (quad >> 1) * 8 + r8;
    const int lcol = (quad & 1) * 8;

    const int qt = blockIdx.x;
    const int h  = blockIdx.y;
    const int b  = blockIdx.z;
    const int gh = h >> 2;

    const size_t koff = ((size_t)(b * NG + gh)) * SEQ * HD;
    const size_t voff = ((size_t)(b * NG + gh)) * HD * SEQ;

    const fp16* qbh = Qh + (((size_t)(b * NH + h)) * SEQ + qt * 128 + wr0) * HD;
    uint32_t qh[4][4];
    #pragma unroll
    for (int kt = 0; kt < 4; kt++) {
        const int o0 = g * HD + kt * 16 + 2 * c;
        qh[kt][0] = *(const uint32_t*)(qbh + o0);
        qh[kt][1] = *(const uint32_t*)(qbh + o0 + 8 * HD);
        qh[kt][2] = *(const uint32_t*)(qbh + o0 + 8);
        qh[kt][3] = *(const uint32_t*)(qbh + o0 + 8 * HD + 8);
    }

    auto fill = [&](int t, int st) {
        const uint32_t s0 = sbase + st * ASTAGE;
        #pragma unroll
        for (int i = 0; i < 2; i++) {
            const int idx = tid + i * 256;
            const int r = idx >> 3, q = (idx & 7) * 8;
            const uint32_t so = (r * AKP + q) * 2;
            const size_t gk = koff + (size_t)(t * 64 + r) * HD + q;
            cp16(s0 + so, Kh + gk);
            const size_t gv = voff + (size_t)r * SEQ + t * 64 + q;
            cp16(s0 + AK_BYTES + so, Vh + gv);
        }
    };

    float m0 = -1e30f, m1 = -1e30f, l0 = 0.0f, l1 = 0.0f;
    float oacc[8][4];
    #pragma unroll
    for (int nt = 0; nt < 8; nt++)
        #pragma unroll
        for (int j = 0; j < 4; j++) oacc[nt][j] = 0.0f;

    fill(0, 0); CP_COMMIT();

    for (int t = 0; t < SEQ / 64; t++) {
        CP_WAIT0();
        __syncthreads();
        if (t + 1 < SEQ / 64) { fill(t + 1, (t + 1) & 1); CP_COMMIT(); }
        const uint32_t sK = sbase + (t & 1) * ASTAGE;
        const uint32_t sV = sK + AK_BYTES;

        // ---- S = Q @ K^T (1-term fp16) ----
        float sv[8][4];
        #pragma unroll
        for (int nt = 0; nt < 8; nt++)
            #pragma unroll
            for (int j = 0; j < 4; j++) sv[nt][j] = 0.0f;

        #pragma unroll
        for (int np = 0; np < 4; np++) {
            #pragma unroll
            for (int kt = 0; kt < 4; kt++) {
                const uint32_t ka = sK + ((np * 16 + lrow) * AKP + kt * 16 + lcol) * 2;
                uint32_t h0, h1, h2, h3;
                ldsm4(h0, h1, h2, h3, ka);
                mma_f16(sv[2*np],   qh[kt], h0, h1);
                mma_f16(sv[2*np+1], qh[kt], h2, h3);
            }
        }

        // ---- online softmax: exp2 via ex2.approx.f16x2 ----
        float mx0 = -1e30f, mx1 = -1e30f;
        #pragma unroll
        for (int nt = 0; nt < 8; nt++) {
            mx0 = fmaxf(mx0, fmaxf(sv[nt][0], sv[nt][1]));
            mx1 = fmaxf(mx1, fmaxf(sv[nt][2], sv[nt][3]));
        }
        mx0 = fmaxf(mx0, __shfl_xor_sync(0xffffffffu, mx0, 1));
        mx0 = fmaxf(mx0, __shfl_xor_sync(0xffffffffu, mx0, 2));
        mx1 = fmaxf(mx1, __shfl_xor_sync(0xffffffffu, mx1, 1));
        mx1 = fmaxf(mx1, __shfl_xor_sync(0xffffffffu, mx1, 2));

        const float nm0 = fmaxf(m0, mx0), nm1 = fmaxf(m1, mx1);
        const float corr0 = exp2f(m0 - nm0), corr1 = exp2f(m1 - nm1);

        // pp[nt][0] = exp2 pair of (sv0,sv1) [row g];  pp[nt][1] = (sv2,sv3) [row g+8]
        uint32_t pp[8][2];
        float ls0 = 0.0f, ls1 = 0.0f;
        #pragma unroll
        for (int nt = 0; nt < 8; nt++) {
            __half2 a0 = __floats2half2_rn(sv[nt][0] - nm0, sv[nt][1] - nm0);
            __half2 a1 = __floats2half2_rn(sv[nt][2] - nm1, sv[nt][3] - nm1);
            pp[nt][0] = h2ex2(*reinterpret_cast<uint32_t*>(&a0));
            pp[nt][1] = h2ex2(*reinterpret_cast<uint32_t*>(&a1));
            const float2 f0 = __half22float2(*reinterpret_cast<__half2*>(&pp[nt][0]));
            const float2 f1 = __half22float2(*reinterpret_cast<__half2*>(&pp[nt][1]));
            ls0 += f0.x + f0.y;
            ls1 += f1.x + f1.y;
        }
        ls0 += __shfl_xor_sync(0xffffffffu, ls0, 1);
        ls0 += __shfl_xor_sync(0xffffffffu, ls0, 2);
        ls1 += __shfl_xor_sync(0xffffffffu, ls1, 1);
        ls1 += __shfl_xor_sync(0xffffffffu, ls1, 2);
        l0 = l0 * corr0 + ls0; m0 = nm0;
        l1 = l1 * corr1 + ls1; m1 = nm1;
        #pragma unroll
        for (int nt = 0; nt < 8; nt++) {
            oacc[nt][0] *= corr0; oacc[nt][1] *= corr0;
            oacc[nt][2] *= corr1; oacc[nt][3] *= corr1;
        }

        // ---- O += P @ V (P = pp directly; V hi in smem) ----
        #pragma unroll
        for (int kt = 0; kt < 4; kt++) {
            const uint32_t ph[4] = {
                pp[2*kt][0], pp[2*kt][1], pp[2*kt+1][0], pp[2*kt+1][1] };
            #pragma unroll
            for (int np = 0; np < 4; np++) {
                const uint32_t va = sV + ((np * 16 + lrow) * AKP + kt * 16 + lcol) * 2;
                uint32_t h0, h1, h2, h3;
                ldsm4(h0, h1, h2, h3, va);
                mma_f16(oacc[2*np],   ph, h0, h1);
                mma_f16(oacc[2*np+1], ph, h2, h3);
            }
        }
    }

    // ---- epilogue: normalize, store fp16 hi to [b,s,h*64+d] ----
    const float inv0 = 1.0f / l0, inv1 = 1.0f / l1;
    const int s0 = qt * 128 + wr0 + g;
    const size_t ob0 = ((size_t)b * SEQ + s0) * HID + h * HD;
    const size_t ob1 = ((size_t)b * SEQ + s0 + 8) * HID + h * HD;
    #pragma unroll
    for (int nt = 0; nt < 8; nt++) {
        const int d = nt * 8 + 2 * c;
        *reinterpret_cast<uint32_t*>(Oh + ob0 + d) =
            pack2h(oacc[nt][0] * inv0, oacc[nt][1] * inv0);
        *reinterpret_cast<uint32_t*>(Oh + ob1 + d) =
            pack2h(oacc[nt][2] * inv1, oacc[nt][3] * inv1);
    }
}

// ---------------------------------------------------------------------------
extern "C" void kernel_launch(void* const* d_in, const int* in_sizes, int n_in,
                              void* d_out, int out_size)
{
    const float* X  = (const float*)d_in[0];
    const float* Wq = (const float*)d_in[1];
    const float* bq = (const float*)d_in[2];
    const float* Wk = (const float*)d_in[3];
    const float* bk = (const float*)d_in[4];
    const float* Wv = (const float*)d_in[5];
    const float* bv = (const float*)d_in[6];
    const float* Wo = (const float*)d_in[7];
    const float* bo = (const float*)d_in[8];
    float* out = (float*)d_out;

    fp16 *xh, *wch, *woh, *qh, *kh, *vh, *oh;
    cudaGetSymbolAddress((void**)&xh,  g_xh);
    cudaGetSymbolAddress((void**)&wch, g_wch); cudaGetSymbolAddress((void**)&woh, g_woh);
    cudaGetSymbolAddress((void**)&qh,  g_qh);
    cudaGetSymbolAddress((void**)&kh,  g_kh);  cudaGetSymbolAddress((void**)&vh,  g_vh);
    cudaGetSymbolAddress((void**)&oh,  g_oh);

    cudaFuncSetAttribute(gemm_kernel<0>, cudaFuncAttributeMaxDynamicSharedMemorySize, GEMM_SMEM);
    cudaFuncSetAttribute(gemm_kernel<4>, cudaFuncAttributeMaxDynamicSharedMemorySize, GEMM_SMEM);
    cudaFuncSetAttribute(attn_kernel, cudaFuncAttributeMaxDynamicSharedMemorySize, ATTN_SMEM);

    // ---- single fused convert ----
    convert_all_kernel<<<(ALLF4 + 255) / 256, 256>>>(
        X, Wq, Wk, Wv, Wo, xh, wch, woh);

    dim3 blk(256);
    // Fused QKV projection (1-term): [4096,2048] @ [2048,3072]
    gemm_kernel<4><<<dim3(NC / 128, MTOT / 128), blk, GEMM_SMEM>>>(
        xh, wch, bq, bk, bv, nullptr, MTOT, NC, HID);
    // Attention -> fp16 hi [b,s,h*d]
    attn_kernel<<<dim3(SEQ / 128, NH, BATCH), blk, ATTN_SMEM>>>(
        qh, kh, vh, oh);
    // Output projection (1-term) -> fp32 d_out
    gemm_kernel<0><<<dim3(HID / 128, MTOT / 128), blk, GEMM_SMEM>>>(
        oh, woh, bo, nullptr, nullptr, out, MTOT, HID, HID);
}

// round 14
// speedup vs baseline: 1.2447x; 1.2447x over previous
#include <cuda_runtime.h>
#include <cuda_fp16.h>
#include <cstdint>

#define BATCH 2
#define SEQ   2048
#define HID   2048
#define NH    32
#define NG    8
#define HD    64
#define KVD   (NG*HD)     // 512
#define MTOT  (BATCH*SEQ) // 4096
#define NC    (HID + 2*KVD)  // 3072 combined QKV cols

typedef __half fp16;

// ---------------- device scratch (no allocation allowed) ----------------
__device__ fp16 g_xh[(size_t)MTOT*HID];                           // hi only
__device__ fp16 g_wch[(size_t)HID*NC];                            // [K, Q|K|V] hi only
__device__ fp16 g_woh[(size_t)HID*HID];                           // [K,N] hi only
__device__ fp16 g_qh[(size_t)BATCH*NH*SEQ*HD];                    // hi only
__device__ fp16 g_kh[(size_t)BATCH*NG*SEQ*HD];                    // hi only
__device__ fp16 g_vh[(size_t)BATCH*NG*HD*SEQ];                    // [b,g,d,s] hi only
__device__ fp16 g_oh[(size_t)MTOT*HID];                           // hi only

// ---------------- helpers ----------------
__device__ __forceinline__ uint32_t pack2h(float x0, float x1) {
    __half2 hb = __floats2half2_rn(x0, x1);
    return *reinterpret_cast<uint32_t*>(&hb);
}

__device__ __forceinline__ void mma_f16(float d[4], const uint32_t a[4],
                                        uint32_t b0, uint32_t b1) {
    asm volatile(
        "mma.sync.aligned.m16n8k16.row.col.f32.f16.f16.f32 "
        "{%0,%1,%2,%3}, {%4,%5,%6,%7}, {%8,%9}, {%0,%1,%2,%3};\n"
        : "+f"(d[0]), "+f"(d[1]), "+f"(d[2]), "+f"(d[3])
        : "r"(a[0]), "r"(a[1]), "r"(a[2]), "r"(a[3]), "r"(b0), "r"(b1));
}

__device__ __forceinline__ void ldsm4(uint32_t& r0, uint32_t& r1, uint32_t& r2,
                                      uint32_t& r3, uint32_t addr) {
    asm volatile("ldmatrix.sync.aligned.m8n8.x4.shared.b16 {%0,%1,%2,%3}, [%4];"
                 : "=r"(r0), "=r"(r1), "=r"(r2), "=r"(r3) : "r"(addr));
}
__device__ __forceinline__ void ldsm4t(uint32_t& r0, uint32_t& r1, uint32_t& r2,
                                       uint32_t& r3, uint32_t addr) {
    asm volatile("ldmatrix.sync.aligned.m8n8.x4.trans.shared.b16 {%0,%1,%2,%3}, [%4];"
                 : "=r"(r0), "=r"(r1), "=r"(r2), "=r"(r3) : "r"(addr));
}

__device__ __forceinline__ void cp16(uint32_t saddr, const void* gaddr) {
    asm volatile("cp.async.cg.shared.global [%0], [%1], 16;"
                 :: "r"(saddr), "l"(gaddr) : "memory");
}
#define CP_COMMIT() asm volatile("cp.async.commit_group;" ::: "memory")
#define CP_WAIT0()  asm volatile("cp.async.wait_group 0;"  ::: "memory")

// exp2 on a packed half2 (one MUFU op for two values)
__device__ __forceinline__ uint32_t h2ex2(uint32_t x) {
    uint32_t r;
    asm("ex2.approx.f16x2 %0, %1;" : "=r"(r) : "r"(x));
    return r;
}

// ---------------- fused fp32 -> fp16 convert (X, Wq|Wk|Wv combined, Wo) ---
#define XF4  ((MTOT*HID)/4)       // 2097152
#define WQF4 ((HID*HID)/4)        // 1048576
#define WKF4 ((HID*KVD)/4)        // 262144
#define ALLF4 (XF4 + WQF4 + 2*WKF4 + WQF4)

__global__ __launch_bounds__(256) void convert_all_kernel(
    const float* __restrict__ X,  const float* __restrict__ Wq,
    const float* __restrict__ Wk, const float* __restrict__ Wv,
    const float* __restrict__ Wo,
    fp16* __restrict__ xh, fp16* __restrict__ wch, fp16* __restrict__ woh)
{
    const int i = blockIdx.x * blockDim.x + threadIdx.x;
    if (i >= ALLF4) return;

    if (i < XF4) {
        float4 v = reinterpret_cast<const float4*>(X)[i];
        reinterpret_cast<uint32_t*>(xh)[i * 2]     = pack2h(v.x, v.y);
        reinterpret_cast<uint32_t*>(xh)[i * 2 + 1] = pack2h(v.z, v.w);
        return;
    }
    int j = i - XF4;
    const float* src;
    int Nsrc, colOff;
    if (j < WQF4)                { src = Wq; Nsrc = HID; colOff = 0; }
    else if (j < WQF4 + WKF4)    { src = Wk; Nsrc = KVD; colOff = HID;       j -= WQF4; }
    else if (j < WQF4 + 2*WKF4)  { src = Wv; Nsrc = KVD; colOff = HID + KVD; j -= WQF4 + WKF4; }
    else {                       // Wo -> woh linear
        j -= WQF4 + 2 * WKF4;
        float4 v = reinterpret_cast<const float4*>(Wo)[j];
        reinterpret_cast<uint32_t*>(woh)[j * 2]     = pack2h(v.x, v.y);
        reinterpret_cast<uint32_t*>(woh)[j * 2 + 1] = pack2h(v.z, v.w);
        return;
    }
    const int perRow = Nsrc >> 2;
    const int k = j / perRow;
    const int c4 = (j - k * perRow) * 4;
    float4 v = reinterpret_cast<const float4*>(src)[j];
    const size_t o = ((size_t)k * NC + colOff + c4) >> 1;
    reinterpret_cast<uint32_t*>(wch)[o]     = pack2h(v.x, v.y);
    reinterpret_cast<uint32_t*>(wch)[o + 1] = pack2h(v.z, v.w);
}

// ---------------------------------------------------------------------------
// 1-term fp16 GEMM (R12 config): CTA 128x128, BK=32, 256 threads
// (8 warps 4x2, warp tile 32x64), cp.async double buffer + ldmatrix.
// MODE 0: fp32 +bias -> Cf (O projection)
// MODE 4: combined QKV epilogue: Q -> hi [b,h,s,d]; K -> hi [b,g,s,d]
//         scaled by 0.125*log2e; V -> hi transposed [b,g,d,s]
// ---------------------------------------------------------------------------
#define GAP 40     // A smem pitch (fp16): 32 k + 8 pad
#define GBP 136    // B smem pitch (fp16): 128 n + 8 pad
#define GA_BYTES (128 * GAP * 2)            // 10240
#define GB_BYTES (32 * GBP * 2)             // 8704
#define GSTAGE   (GA_BYTES + GB_BYTES)      // 18944
#define GEMM_SMEM (2 * GSTAGE)              // 37888
#define KSCALE (0.125f * 1.44269504088896f)

template<int MODE>
__global__ __launch_bounds__(256, 2) void gemm_kernel(
    const fp16* __restrict__ Ah, const fp16* __restrict__ Bh,
    const float* __restrict__ bias0, const float* __restrict__ bias1,
    const float* __restrict__ bias2,
    float* __restrict__ Cf, int M, int N, int K)
{
    extern __shared__ char smc[];
    const uint32_t sbase = (uint32_t)__cvta_generic_to_shared(smc);

    const int tid  = threadIdx.x;
    const int lane = tid & 31;
    const int wid  = tid >> 5;
    const int g = lane >> 2, c = lane & 3;
    const int quad = lane >> 3, r8 = lane & 7;
    const int wm0 = (wid & 3) * 32;
    const int wn0 = (wid >> 2) * 64;
    const int row0 = blockIdx.y * 128;
    const int col0 = blockIdx.x * 128;

    float acc[2][8][4];
    #pragma unroll
    for (int mt = 0; mt < 2; mt++)
        #pragma unroll
        for (int nt = 0; nt < 8; nt++)
            #pragma unroll
            for (int j = 0; j < 4; j++) acc[mt][nt][j] = 0.0f;

    const int NT = K / 32;

    auto fill = [&](int kt, int st) {
        const int k0 = kt * 32;
        const uint32_t s0 = sbase + st * GSTAGE;
        // A: 128 rows x 32 k (512 f4, 2 per thread)
        #pragma unroll
        for (int i = 0; i < 2; i++) {
            const int idx = tid + i * 256;
            const int r = idx >> 2, q = (idx & 3) * 8;
            const size_t go = (size_t)(row0 + r) * K + k0 + q;
            cp16(s0 + (r * GAP + q) * 2, Ah + go);
        }
        // B: 32 k-rows x 128 n (512 f4, 2 per thread)
        #pragma unroll
        for (int i = 0; i < 2; i++) {
            const int idx = tid + i * 256;
            const int r = idx >> 4, q = (idx & 15) * 8;
            const size_t go = (size_t)(k0 + r) * N + col0 + q;
            cp16(s0 + GA_BYTES + (r * GBP + q) * 2, Bh + go);
        }
    };

    fill(0, 0); CP_COMMIT();

    const int arow = (quad & 1) * 8 + r8;
    const int acol = (quad >> 1) * 8;

    for (int kt = 0; kt < NT; kt++) {
        CP_WAIT0();
        __syncthreads();
        if (kt + 1 < NT) { fill(kt + 1, (kt + 1) & 1); CP_COMMIT(); }
        const uint32_t s0 = sbase + (kt & 1) * GSTAGE;

        #pragma unroll
        for (int kk = 0; kk < 2; kk++) {
            uint32_t ah[2][4];
            #pragma unroll
            for (int mt = 0; mt < 2; mt++) {
                const uint32_t aaddr =
                    s0 + ((wm0 + mt * 16 + arow) * GAP + kk * 16 + acol) * 2;
                ldsm4(ah[mt][0], ah[mt][1], ah[mt][2], ah[mt][3], aaddr);
            }
            #pragma unroll
            for (int np = 0; np < 4; np++) {
                const uint32_t baddr = s0 + GA_BYTES +
                    ((kk * 16 + arow) * GBP + wn0 + np * 16 + acol) * 2;
                uint32_t bh0, bh1, bh2, bh3;
                ldsm4t(bh0, bh1, bh2, bh3, baddr);
                #pragma unroll
                for (int mt = 0; mt < 2; mt++) {
                    mma_f16(acc[mt][2*np],   ah[mt], bh0, bh1);
                    mma_f16(acc[mt][2*np+1], ah[mt], bh2, bh3);
                }
            }
        }
    }

    // ---- epilogue ----
    #pragma unroll
    for (int mt = 0; mt < 2; mt++) {
        const int r = row0 + wm0 + mt * 16 + g;     // and r+8
        const int b0 = r >> 11, s0i = r & 2047;
        const int b1 = (r + 8) >> 11, s1i = (r + 8) & 2047;
        #pragma unroll
        for (int nt = 0; nt < 8; nt++) {
            const int n = col0 + wn0 + nt * 8 + 2 * c;
            if (MODE == 0) {
                const float bv0 = bias0[n], bv1 = bias0[n + 1];
                const float v0 = acc[mt][nt][0] + bv0;
                const float v1 = acc[mt][nt][1] + bv1;
                const float v2 = acc[mt][nt][2] + bv0;
                const float v3 = acc[mt][nt][3] + bv1;
                *(float2*)(Cf + (size_t)r * N + n)       = make_float2(v0, v1);
                *(float2*)(Cf + (size_t)(r + 8) * N + n) = make_float2(v2, v3);
            } else {
                if (n < HID) {               // ---- Q: hi [b,h,s,d] ----
                    const float bv0 = bias0[n], bv1 = bias0[n + 1];
                    const int hh = n >> 6, d = n & 63;
                    size_t o0 = (((size_t)(b0 * NH + hh)) * SEQ + s0i) * HD + d;
                    size_t o1 = (((size_t)(b1 * NH + hh)) * SEQ + s1i) * HD + d;
                    *reinterpret_cast<uint32_t*>(g_qh + o0) =
                        pack2h(acc[mt][nt][0] + bv0, acc[mt][nt][1] + bv1);
                    *reinterpret_cast<uint32_t*>(g_qh + o1) =
                        pack2h(acc[mt][nt][2] + bv0, acc[mt][nt][3] + bv1);
                } else if (n < HID + KVD) {  // ---- K: hi [b,g,s,d], xKSCALE ----
                    const int nn = n - HID;
                    const float bv0 = bias1[nn], bv1 = bias1[nn + 1];
                    const float v0 = (acc[mt][nt][0] + bv0) * KSCALE;
                    const float v1 = (acc[mt][nt][1] + bv1) * KSCALE;
                    const float v2 = (acc[mt][nt][2] + bv0) * KSCALE;
                    const float v3 = (acc[mt][nt][3] + bv1) * KSCALE;
                    const int gg = nn >> 6, d = nn & 63;
                    size_t o0 = (((size_t)(b0 * NG + gg)) * SEQ + s0i) * HD + d;
                    size_t o1 = (((size_t)(b1 * NG + gg)) * SEQ + s1i) * HD + d;
                    *reinterpret_cast<uint32_t*>(g_kh + o0) = pack2h(v0, v1);
                    *reinterpret_cast<uint32_t*>(g_kh + o1) = pack2h(v2, v3);
                } else {                     // ---- V: hi transposed [b,g,d,s] ----
                    const int nn = n - HID - KVD;
                    const float bv0 = bias2[nn], bv1 = bias2[nn + 1];
                    const float vals[4] = {
                        acc[mt][nt][0] + bv0, acc[mt][nt][1] + bv1,
                        acc[mt][nt][2] + bv0, acc[mt][nt][3] + bv1 };
                    const int gg = nn >> 6, d = nn & 63;
                    const size_t base0 = ((size_t)(b0 * NG + gg)) * HD;
                    const size_t base1 = ((size_t)(b1 * NG + gg)) * HD;
                    const size_t offs[4] = {
                        (base0 + d) * SEQ + s0i, (base0 + d + 1) * SEQ + s0i,
                        (base1 + d) * SEQ + s1i, (base1 + d + 1) * SEQ + s1i };
                    #pragma unroll
                    for (int j = 0; j < 4; j++)
                        g_vh[offs[j]] = __float2half_rn(vals[j]);
                }
            }
        }
    }
}

// ---------------------------------------------------------------------------
// Flash attention: 1-term fp16 QK + 1-term PV, K/V hi-only in smem,
// ex2.approx.f16x2 softmax (one MUFU per score pair; output IS the P frag).
// Block = (b, h, 128-query tile), 256 threads.
// ---------------------------------------------------------------------------
#define AKP 72
#define AK_BYTES (64 * AKP * 2)        // 9216
#define ASTAGE   (2 * AK_BYTES)        // 18432
#define ATTN_SMEM (2 * ASTAGE)         // 36864

__global__ __launch_bounds__(256, 2) void attn_kernel(
    const fp16* __restrict__ Qh, const fp16* __restrict__ Kh,
    const fp16* __restrict__ Vh, fp16* __restrict__ Oh)
{
    extern __shared__ char smc[];
    const uint32_t sbase = (uint32_t)__cvta_generic_to_shared(smc);

    const int tid  = threadIdx.x;
    const int lane = tid & 31;
    const int wid  = tid >> 5;
    const int g = lane >> 2, c = lane & 3;
    const int quad = lane >> 3, r8 = lane & 7;
    const int wr0 = wid * 16;
    const int lrow = (quad >> 1) * 8 + r8;
    const int lcol = (quad & 1) * 8;

    const int qt = blockIdx.x;
    const int h  = blockIdx.y;
    const int b  = blockIdx.z;
    const int gh = h >> 2;

    const size_t koff = ((size_t)(b * NG + gh)) * SEQ * HD;
    const size_t voff = ((size_t)(b * NG + gh)) * HD * SEQ;

    const fp16* qbh = Qh + (((size_t)(b * NH + h)) * SEQ + qt * 128 + wr0) * HD;
    uint32_t qh[4][4];
    #pragma unroll
    for (int kt = 0; kt < 4; kt++) {
        const int o0 = g * HD + kt * 16 + 2 * c;
        qh[kt][0] = *(const uint32_t*)(qbh + o0);
        qh[kt][1] = *(const uint32_t*)(qbh + o0 + 8 * HD);
        qh[kt][2] = *(const uint32_t*)(qbh + o0 + 8);
        qh[kt][3] = *(const uint32_t*)(qbh + o0 + 8 * HD + 8);
    }

    auto fill = [&](int t, int st) {
        const uint32_t s0 = sbase + st * ASTAGE;
        #pragma unroll
        for (int i = 0; i < 2; i++) {
            const int idx = tid + i * 256;
            const int r = idx >> 3, q = (idx & 7) * 8;
            const uint32_t so = (r * AKP + q) * 2;
            const size_t gk = koff + (size_t)(t * 64 + r) * HD + q;
            cp16(s0 + so, Kh + gk);
            const size_t gv = voff + (size_t)r * SEQ + t * 64 + q;
            cp16(s0 + AK_BYTES + so, Vh + gv);
        }
    };

    float m0 = -1e30f, m1 = -1e30f, l0 = 0.0f, l1 = 0.0f;
    float oacc[8][4];
    #pragma unroll
    for (int nt = 0; nt < 8; nt++)
        #pragma unroll
        for (int j = 0; j < 4; j++) oacc[nt][j] = 0.0f;

    fill(0, 0); CP_COMMIT();

    for (int t = 0; t < SEQ / 64; t++) {
        CP_WAIT0();
        __syncthreads();
        if (t + 1 < SEQ / 64) { fill(t + 1, (t + 1) & 1); CP_COMMIT(); }
        const uint32_t sK = sbase + (t & 1) * ASTAGE;
        const uint32_t sV = sK + AK_BYTES;

        // ---- S = Q @ K^T (1-term fp16) ----
        float sv[8][4];
        #pragma unroll
        for (int nt = 0; nt < 8; nt++)
            #pragma unroll
            for (int j = 0; j < 4; j++) sv[nt][j] = 0.0f;

        #pragma unroll
        for (int np = 0; np < 4; np++) {
            #pragma unroll
            for (int kt = 0; kt < 4; kt++) {
                const uint32_t ka = sK + ((np * 16 + lrow) * AKP + kt * 16 + lcol) * 2;
                uint32_t h0, h1, h2, h3;
                ldsm4(h0, h1, h2, h3, ka);
                mma_f16(sv[2*np],   qh[kt], h0, h1);
                mma_f16(sv[2*np+1], qh[kt], h2, h3);
            }
        }

        // ---- online softmax: exp2 via ex2.approx.f16x2 ----
        float mx0 = -1e30f, mx1 = -1e30f;
        #pragma unroll
        for (int nt = 0; nt < 8; nt++) {
            mx0 = fmaxf(mx0, fmaxf(sv[nt][0], sv[nt][1]));
            mx1 = fmaxf(mx1, fmaxf(sv[nt][2], sv[nt][3]));
        }
        mx0 = fmaxf(mx0, __shfl_xor_sync(0xffffffffu, mx0, 1));
        mx0 = fmaxf(mx0, __shfl_xor_sync(0xffffffffu, mx0, 2));
        mx1 = fmaxf(mx1, __shfl_xor_sync(0xffffffffu, mx1, 1));
        mx1 = fmaxf(mx1, __shfl_xor_sync(0xffffffffu, mx1, 2));

        const float nm0 = fmaxf(m0, mx0), nm1 = fmaxf(m1, mx1);
        const float corr0 = exp2f(m0 - nm0), corr1 = exp2f(m1 - nm1);

        uint32_t pp[8][2];
        float ls0 = 0.0f, ls1 = 0.0f;
        #pragma unroll
        for (int nt = 0; nt < 8; nt++) {
            __half2 a0 = __floats2half2_rn(sv[nt][0] - nm0, sv[nt][1] - nm0);
            __half2 a1 = __floats2half2_rn(sv[nt][2] - nm1, sv[nt][3] - nm1);
            pp[nt][0] = h2ex2(*reinterpret_cast<uint32_t*>(&a0));
            pp[nt][1] = h2ex2(*reinterpret_cast<uint32_t*>(&a1));
            const float2 f0 = __half22float2(*reinterpret_cast<__half2*>(&pp[nt][0]));
            const float2 f1 = __half22float2(*reinterpret_cast<__half2*>(&pp[nt][1]));
            ls0 += f0.x + f0.y;
            ls1 += f1.x + f1.y;
        }
        ls0 += __shfl_xor_sync(0xffffffffu, ls0, 1);
        ls0 += __shfl_xor_sync(0xffffffffu, ls0, 2);
        ls1 += __shfl_xor_sync(0xffffffffu, ls1, 1);
        ls1 += __shfl_xor_sync(0xffffffffu, ls1, 2);
        l0 = l0 * corr0 + ls0; m0 = nm0;
        l1 = l1 * corr1 + ls1; m1 = nm1;
        #pragma unroll
        for (int nt = 0; nt < 8; nt++) {
            oacc[nt][0] *= corr0; oacc[nt][1] *= corr0;
            oacc[nt][2] *= corr1; oacc[nt][3] *= corr1;
        }

        // ---- O += P @ V (P = pp directly; V hi in smem) ----
        #pragma unroll
        for (int kt = 0; kt < 4; kt++) {
            const uint32_t ph[4] = {
                pp[2*kt][0], pp[2*kt][1], pp[2*kt+1][0], pp[2*kt+1][1] };
            #pragma unroll
            for (int np = 0; np < 4; np++) {
                const uint32_t va = sV + ((np * 16 + lrow) * AKP + kt * 16 + lcol) * 2;
                uint32_t h0, h1, h2, h3;
                ldsm4(h0, h1, h2, h3, va);
                mma_f16(oacc[2*np],   ph, h0, h1);
                mma_f16(oacc[2*np+1], ph, h2, h3);
            }
        }
    }

    // ---- epilogue: normalize, store fp16 hi to [b,s,h*64+d] ----
    const float inv0 = 1.0f / l0, inv1 = 1.0f / l1;
    const int s0 = qt * 128 + wr0 + g;
    const size_t ob0 = ((size_t)b * SEQ + s0) * HID + h * HD;
    const size_t ob1 = ((size_t)b * SEQ + s0 + 8) * HID + h * HD;
    #pragma unroll
    for (int nt = 0; nt < 8; nt++) {
        const int d = nt * 8 + 2 * c;
        *reinterpret_cast<uint32_t*>(Oh + ob0 + d) =
            pack2h(oacc[nt][0] * inv0, oacc[nt][1] * inv0);
        *reinterpret_cast<uint32_t*>(Oh + ob1 + d) =
            pack2h(oacc[nt][2] * inv1, oacc[nt][3] * inv1);
    }
}

// ---------------------------------------------------------------------------
extern "C" void kernel_launch(void* const* d_in, const int* in_sizes, int n_in,
                              void* d_out, int out_size)
{
    const float* X  = (const float*)d_in[0];
    const float* Wq = (const float*)d_in[1];
    const float* bq = (const float*)d_in[2];
    const float* Wk = (const float*)d_in[3];
    const float* bk = (const float*)d_in[4];
    const float* Wv = (const float*)d_in[5];
    const float* bv = (const float*)d_in[6];
    const float* Wo = (const float*)d_in[7];
    const float* bo = (const float*)d_in[8];
    float* out = (float*)d_out;

    fp16 *xh, *wch, *woh, *qh, *kh, *vh, *oh;
    cudaGetSymbolAddress((void**)&xh,  g_xh);
    cudaGetSymbolAddress((void**)&wch, g_wch); cudaGetSymbolAddress((void**)&woh, g_woh);
    cudaGetSymbolAddress((void**)&qh,  g_qh);
    cudaGetSymbolAddress((void**)&kh,  g_kh);  cudaGetSymbolAddress((void**)&vh,  g_vh);
    cudaGetSymbolAddress((void**)&oh,  g_oh);

    cudaFuncSetAttribute(gemm_kernel<0>, cudaFuncAttributeMaxDynamicSharedMemorySize, GEMM_SMEM);
    cudaFuncSetAttribute(gemm_kernel<4>, cudaFuncAttributeMaxDynamicSharedMemorySize, GEMM_SMEM);
    cudaFuncSetAttribute(attn_kernel, cudaFuncAttributeMaxDynamicSharedMemorySize, ATTN_SMEM);

    // ---- single fused convert ----
    convert_all_kernel<<<(ALLF4 + 255) / 256, 256>>>(
        X, Wq, Wk, Wv, Wo, xh, wch, woh);

    dim3 blk(256);
    // Fused QKV projection (1-term): [4096,2048] @ [2048,3072]
    gemm_kernel<4><<<dim3(NC / 128, MTOT / 128), blk, GEMM_SMEM>>>(
        xh, wch, bq, bk, bv, nullptr, MTOT, NC, HID);
    // Attention -> fp16 hi [b,s,h*d]
    attn_kernel<<<dim3(SEQ / 128, NH, BATCH), blk, ATTN_SMEM>>>(
        qh, kh, vh, oh);
    // Output projection (1-term) -> fp32 d_out
    gemm_kernel<0><<<dim3(HID / 128, MTOT / 128), blk, GEMM_SMEM>>>(
        oh, woh, bo, nullptr, nullptr, out, MTOT, HID, HID);
}

// round 15
// speedup vs baseline: 1.2451x; 1.0002x over previous
#include <cuda_runtime.h>
#include <cuda_fp16.h>
#include <cstdint>

#define BATCH 2
#define SEQ   2048
#define HID   2048
#define NH    32
#define NG    8
#define HD    64
#define KVD   (NG*HD)     // 512
#define MTOT  (BATCH*SEQ) // 4096
#define NC    (HID + 2*KVD)  // 3072 combined QKV cols

typedef __half fp16;

// ---------------- device scratch (no allocation allowed) ----------------
__device__ fp16 g_xh[(size_t)MTOT*HID];                           // hi only
__device__ fp16 g_wch[(size_t)HID*NC];                            // [K, Q|K|V] hi only
__device__ fp16 g_woh[(size_t)HID*HID];                           // [K,N] hi only
__device__ fp16 g_qh[(size_t)BATCH*NH*SEQ*HD];                    // hi only
__device__ fp16 g_kh[(size_t)BATCH*NG*SEQ*HD];                    // hi only
__device__ fp16 g_vh[(size_t)BATCH*NG*HD*SEQ];                    // [b,g,d,s] hi only
__device__ fp16 g_oh[(size_t)MTOT*HID];                           // hi only

// ---------------- helpers ----------------
__device__ __forceinline__ uint32_t pack2h(float x0, float x1) {
    __half2 hb = __floats2half2_rn(x0, x1);
    return *reinterpret_cast<uint32_t*>(&hb);
}

__device__ __forceinline__ void mma_f16(float d[4], const uint32_t a[4],
                                        uint32_t b0, uint32_t b1) {
    asm volatile(
        "mma.sync.aligned.m16n8k16.row.col.f32.f16.f16.f32 "
        "{%0,%1,%2,%3}, {%4,%5,%6,%7}, {%8,%9}, {%0,%1,%2,%3};\n"
        : "+f"(d[0]), "+f"(d[1]), "+f"(d[2]), "+f"(d[3])
        : "r"(a[0]), "r"(a[1]), "r"(a[2]), "r"(a[3]), "r"(b0), "r"(b1));
}

__device__ __forceinline__ void ldsm4(uint32_t* r, uint32_t addr) {
    asm volatile("ldmatrix.sync.aligned.m8n8.x4.shared.b16 {%0,%1,%2,%3}, [%4];"
                 : "=r"(r[0]), "=r"(r[1]), "=r"(r[2]), "=r"(r[3]) : "r"(addr));
}
__device__ __forceinline__ void ldsm4t(uint32_t* r, uint32_t addr) {
    asm volatile("ldmatrix.sync.aligned.m8n8.x4.trans.shared.b16 {%0,%1,%2,%3}, [%4];"
                 : "=r"(r[0]), "=r"(r[1]), "=r"(r[2]), "=r"(r[3]) : "r"(addr));
}

__device__ __forceinline__ void cp16(uint32_t saddr, const void* gaddr) {
    asm volatile("cp.async.cg.shared.global [%0], [%1], 16;"
                 :: "r"(saddr), "l"(gaddr) : "memory");
}
#define CP_COMMIT() asm volatile("cp.async.commit_group;" ::: "memory")
#define CP_WAIT0()  asm volatile("cp.async.wait_group 0;"  ::: "memory")

// exp2 on a packed half2 (one MUFU op for two values)
__device__ __forceinline__ uint32_t h2ex2(uint32_t x) {
    uint32_t r;
    asm("ex2.approx.f16x2 %0, %1;" : "=r"(r) : "r"(x));
    return r;
}

// ---------------- fused fp32 -> fp16 convert (X, Wq|Wk|Wv combined, Wo) ---
#define XF4  ((MTOT*HID)/4)       // 2097152
#define WQF4 ((HID*HID)/4)        // 1048576
#define WKF4 ((HID*KVD)/4)        // 262144
#define ALLF4 (XF4 + WQF4 + 2*WKF4 + WQF4)

__global__ __launch_bounds__(256) void convert_all_kernel(
    const float* __restrict__ X,  const float* __restrict__ Wq,
    const float* __restrict__ Wk, const float* __restrict__ Wv,
    const float* __restrict__ Wo,
    fp16* __restrict__ xh, fp16* __restrict__ wch, fp16* __restrict__ woh)
{
    const int i = blockIdx.x * blockDim.x + threadIdx.x;
    if (i >= ALLF4) return;

    if (i < XF4) {
        float4 v = reinterpret_cast<const float4*>(X)[i];
        reinterpret_cast<uint32_t*>(xh)[i * 2]     = pack2h(v.x, v.y);
        reinterpret_cast<uint32_t*>(xh)[i * 2 + 1] = pack2h(v.z, v.w);
        return;
    }
    int j = i - XF4;
    const float* src;
    int Nsrc, colOff;
    if (j < WQF4)                { src = Wq; Nsrc = HID; colOff = 0; }
    else if (j < WQF4 + WKF4)    { src = Wk; Nsrc = KVD; colOff = HID;       j -= WQF4; }
    else if (j < WQF4 + 2*WKF4)  { src = Wv; Nsrc = KVD; colOff = HID + KVD; j -= WQF4 + WKF4; }
    else {                       // Wo -> woh linear
        j -= WQF4 + 2 * WKF4;
        float4 v = reinterpret_cast<const float4*>(Wo)[j];
        reinterpret_cast<uint32_t*>(woh)[j * 2]     = pack2h(v.x, v.y);
        reinterpret_cast<uint32_t*>(woh)[j * 2 + 1] = pack2h(v.z, v.w);
        return;
    }
    const int perRow = Nsrc >> 2;
    const int k = j / perRow;
    const int c4 = (j - k * perRow) * 4;
    float4 v = reinterpret_cast<const float4*>(src)[j];
    const size_t o = ((size_t)k * NC + colOff + c4) >> 1;
    reinterpret_cast<uint32_t*>(wch)[o]     = pack2h(v.x, v.y);
    reinterpret_cast<uint32_t*>(wch)[o + 1] = pack2h(v.z, v.w);
}

// ---------------------------------------------------------------------------
// 1-term fp16 GEMM: CTA 128x128, BK=32, 256 threads (8 warps 4x2, warp tile
// 32x64), cp.async double buffer + ldmatrix. ALL fragment LDSMs of a k16-step
// are issued before any consuming MMA (hides the ~30cyc LDS latency once).
// MODE 0: fp32 +bias -> Cf (O projection)
// MODE 4: combined QKV epilogue: Q/K/V scatter (K scaled 0.125*log2e)
// ---------------------------------------------------------------------------
#define GAP 40     // A smem pitch (fp16): 32 k + 8 pad
#define GBP 136    // B smem pitch (fp16): 128 n + 8 pad
#define GA_BYTES (128 * GAP * 2)            // 10240
#define GB_BYTES (32 * GBP * 2)             // 8704
#define GSTAGE   (GA_BYTES + GB_BYTES)      // 18944
#define GEMM_SMEM (2 * GSTAGE)              // 37888
#define KSCALE (0.125f * 1.44269504088896f)

template<int MODE>
__global__ __launch_bounds__(256, 2) void gemm_kernel(
    const fp16* __restrict__ Ah, const fp16* __restrict__ Bh,
    const float* __restrict__ bias0, const float* __restrict__ bias1,
    const float* __restrict__ bias2,
    float* __restrict__ Cf, int M, int N, int K)
{
    extern __shared__ char smc[];
    const uint32_t sbase = (uint32_t)__cvta_generic_to_shared(smc);

    const int tid  = threadIdx.x;
    const int lane = tid & 31;
    const int wid  = tid >> 5;
    const int g = lane >> 2, c = lane & 3;
    const int quad = lane >> 3, r8 = lane & 7;
    const int wm0 = (wid & 3) * 32;
    const int wn0 = (wid >> 2) * 64;
    const int row0 = blockIdx.y * 128;
    const int col0 = blockIdx.x * 128;

    float acc[2][8][4];
    #pragma unroll
    for (int mt = 0; mt < 2; mt++)
        #pragma unroll
        for (int nt = 0; nt < 8; nt++)
            #pragma unroll
            for (int j = 0; j < 4; j++) acc[mt][nt][j] = 0.0f;

    const int NT = K / 32;

    auto fill = [&](int kt, int st) {
        const int k0 = kt * 32;
        const uint32_t s0 = sbase + st * GSTAGE;
        #pragma unroll
        for (int i = 0; i < 2; i++) {
            const int idx = tid + i * 256;
            const int r = idx >> 2, q = (idx & 3) * 8;
            const size_t go = (size_t)(row0 + r) * K + k0 + q;
            cp16(s0 + (r * GAP + q) * 2, Ah + go);
        }
        #pragma unroll
        for (int i = 0; i < 2; i++) {
            const int idx = tid + i * 256;
            const int r = idx >> 4, q = (idx & 15) * 8;
            const size_t go = (size_t)(k0 + r) * N + col0 + q;
            cp16(s0 + GA_BYTES + (r * GBP + q) * 2, Bh + go);
        }
    };

    fill(0, 0); CP_COMMIT();

    const int arow = (quad & 1) * 8 + r8;
    const int acol = (quad >> 1) * 8;

    for (int kt = 0; kt < NT; kt++) {
        CP_WAIT0();
        __syncthreads();
        if (kt + 1 < NT) { fill(kt + 1, (kt + 1) & 1); CP_COMMIT(); }
        const uint32_t s0 = sbase + (kt & 1) * GSTAGE;

        #pragma unroll
        for (int kk = 0; kk < 2; kk++) {
            // ---- batch ALL fragment loads first ----
            uint32_t ah[2][4], bf[4][4];
            #pragma unroll
            for (int mt = 0; mt < 2; mt++) {
                const uint32_t aaddr =
                    s0 + ((wm0 + mt * 16 + arow) * GAP + kk * 16 + acol) * 2;
                ldsm4(ah[mt], aaddr);
            }
            #pragma unroll
            for (int np = 0; np < 4; np++) {
                const uint32_t baddr = s0 + GA_BYTES +
                    ((kk * 16 + arow) * GBP + wn0 + np * 16 + acol) * 2;
                ldsm4t(bf[np], baddr);
            }
            // ---- then run all MMAs back-to-back ----
            #pragma unroll
            for (int np = 0; np < 4; np++)
                #pragma unroll
                for (int mt = 0; mt < 2; mt++) {
                    mma_f16(acc[mt][2*np],   ah[mt], bf[np][0], bf[np][1]);
                    mma_f16(acc[mt][2*np+1], ah[mt], bf[np][2], bf[np][3]);
                }
        }
    }

    // ---- epilogue ----
    #pragma unroll
    for (int mt = 0; mt < 2; mt++) {
        const int r = row0 + wm0 + mt * 16 + g;     // and r+8
        const int b0 = r >> 11, s0i = r & 2047;
        const int b1 = (r + 8) >> 11, s1i = (r + 8) & 2047;
        #pragma unroll
        for (int nt = 0; nt < 8; nt++) {
            const int n = col0 + wn0 + nt * 8 + 2 * c;
            if (MODE == 0) {
                const float bv0 = bias0[n], bv1 = bias0[n + 1];
                const float v0 = acc[mt][nt][0] + bv0;
                const float v1 = acc[mt][nt][1] + bv1;
                const float v2 = acc[mt][nt][2] + bv0;
                const float v3 = acc[mt][nt][3] + bv1;
                *(float2*)(Cf + (size_t)r * N + n)       = make_float2(v0, v1);
                *(float2*)(Cf + (size_t)(r + 8) * N + n) = make_float2(v2, v3);
            } else {
                if (n < HID) {               // ---- Q: hi [b,h,s,d] ----
                    const float bv0 = bias0[n], bv1 = bias0[n + 1];
                    const int hh = n >> 6, d = n & 63;
                    size_t o0 = (((size_t)(b0 * NH + hh)) * SEQ + s0i) * HD + d;
                    size_t o1 = (((size_t)(b1 * NH + hh)) * SEQ + s1i) * HD + d;
                    *reinterpret_cast<uint32_t*>(g_qh + o0) =
                        pack2h(acc[mt][nt][0] + bv0, acc[mt][nt][1] + bv1);
                    *reinterpret_cast<uint32_t*>(g_qh + o1) =
                        pack2h(acc[mt][nt][2] + bv0, acc[mt][nt][3] + bv1);
                } else if (n < HID + KVD) {  // ---- K: hi [b,g,s,d], xKSCALE ----
                    const int nn = n - HID;
                    const float bv0 = bias1[nn], bv1 = bias1[nn + 1];
                    const float v0 = (acc[mt][nt][0] + bv0) * KSCALE;
                    const float v1 = (acc[mt][nt][1] + bv1) * KSCALE;
                    const float v2 = (acc[mt][nt][2] + bv0) * KSCALE;
                    const float v3 = (acc[mt][nt][3] + bv1) * KSCALE;
                    const int gg = nn >> 6, d = nn & 63;
                    size_t o0 = (((size_t)(b0 * NG + gg)) * SEQ + s0i) * HD + d;
                    size_t o1 = (((size_t)(b1 * NG + gg)) * SEQ + s1i) * HD + d;
                    *reinterpret_cast<uint32_t*>(g_kh + o0) = pack2h(v0, v1);
                    *reinterpret_cast<uint32_t*>(g_kh + o1) = pack2h(v2, v3);
                } else {                     // ---- V: hi transposed [b,g,d,s] ----
                    const int nn = n - HID - KVD;
                    const float bv0 = bias2[nn], bv1 = bias2[nn + 1];
                    const float vals[4] = {
                        acc[mt][nt][0] + bv0, acc[mt][nt][1] + bv1,
                        acc[mt][nt][2] + bv0, acc[mt][nt][3] + bv1 };
                    const int gg = nn >> 6, d = nn & 63;
                    const size_t base0 = ((size_t)(b0 * NG + gg)) * HD;
                    const size_t base1 = ((size_t)(b1 * NG + gg)) * HD;
                    const size_t offs[4] = {
                        (base0 + d) * SEQ + s0i, (base0 + d + 1) * SEQ + s0i,
                        (base1 + d) * SEQ + s1i, (base1 + d + 1) * SEQ + s1i };
                    #pragma unroll
                    for (int j = 0; j < 4; j++)
                        g_vh[offs[j]] = __float2half_rn(vals[j]);
                }
            }
        }
    }
}

// ---------------------------------------------------------------------------
// Flash attention: 1-term fp16 QK + 1-term PV, K/V hi-only in smem,
// ex2.approx.f16x2 softmax. Fragment LDSMs batched ahead of their MMAs.
// Block = (b, h, 128-query tile), 256 threads.
// ---------------------------------------------------------------------------
#define AKP 72
#define AK_BYTES (64 * AKP * 2)        // 9216
#define ASTAGE   (2 * AK_BYTES)        // 18432
#define ATTN_SMEM (2 * ASTAGE)         // 36864

__global__ __launch_bounds__(256, 2) void attn_kernel(
    const fp16* __restrict__ Qh, const fp16* __restrict__ Kh,
    const fp16* __restrict__ Vh, fp16* __restrict__ Oh)
{
    extern __shared__ char smc[];
    const uint32_t sbase = (uint32_t)__cvta_generic_to_shared(smc);

    const int tid  = threadIdx.x;
    const int lane = tid & 31;
    const int wid  = tid >> 5;
    const int g = lane >> 2, c = lane & 3;
    const int quad = lane >> 3, r8 = lane & 7;
    const int wr0 = wid * 16;
    const int lrow = (quad >> 1) * 8 + r8;
    const int lcol = (quad & 1) * 8;

    const int qt = blockIdx.x;
    const int h  = blockIdx.y;
    const int b  = blockIdx.z;
    const int gh = h >> 2;

    const size_t koff = ((size_t)(b * NG + gh)) * SEQ * HD;
    const size_t voff = ((size_t)(b * NG + gh)) * HD * SEQ;

    const fp16* qbh = Qh + (((size_t)(b * NH + h)) * SEQ + qt * 128 + wr0) * HD;
    uint32_t qh[4][4];
    #pragma unroll
    for (int kt = 0; kt < 4; kt++) {
        const int o0 = g * HD + kt * 16 + 2 * c;
        qh[kt][0] = *(const uint32_t*)(qbh + o0);
        qh[kt][1] = *(const uint32_t*)(qbh + o0 + 8 * HD);
        qh[kt][2] = *(const uint32_t*)(qbh + o0 + 8);
        qh[kt][3] = *(const uint32_t*)(qbh + o0 + 8 * HD + 8);
    }

    auto fill = [&](int t, int st) {
        const uint32_t s0 = sbase + st * ASTAGE;
        #pragma unroll
        for (int i = 0; i < 2; i++) {
            const int idx = tid + i * 256;
            const int r = idx >> 3, q = (idx & 7) * 8;
            const uint32_t so = (r * AKP + q) * 2;
            const size_t gk = koff + (size_t)(t * 64 + r) * HD + q;
            cp16(s0 + so, Kh + gk);
            const size_t gv = voff + (size_t)r * SEQ + t * 64 + q;
            cp16(s0 + AK_BYTES + so, Vh + gv);
        }
    };

    float m0 = -1e30f, m1 = -1e30f, l0 = 0.0f, l1 = 0.0f;
    float oacc[8][4];
    #pragma unroll
    for (int nt = 0; nt < 8; nt++)
        #pragma unroll
        for (int j = 0; j < 4; j++) oacc[nt][j] = 0.0f;

    fill(0, 0); CP_COMMIT();

    for (int t = 0; t < SEQ / 64; t++) {
        CP_WAIT0();
        __syncthreads();
        if (t + 1 < SEQ / 64) { fill(t + 1, (t + 1) & 1); CP_COMMIT(); }
        const uint32_t sK = sbase + (t & 1) * ASTAGE;
        const uint32_t sV = sK + AK_BYTES;

        // ---- S = Q @ K^T (frag loads batched per np) ----
        float sv[8][4];
        #pragma unroll
        for (int nt = 0; nt < 8; nt++)
            #pragma unroll
            for (int j = 0; j < 4; j++) sv[nt][j] = 0.0f;

        #pragma unroll
        for (int np = 0; np < 4; np++) {
            uint32_t kf[4][4];
            #pragma unroll
            for (int kt = 0; kt < 4; kt++)
                ldsm4(kf[kt], sK + ((np * 16 + lrow) * AKP + kt * 16 + lcol) * 2);
            #pragma unroll
            for (int kt = 0; kt < 4; kt++) {
                mma_f16(sv[2*np],   qh[kt], kf[kt][0], kf[kt][1]);
                mma_f16(sv[2*np+1], qh[kt], kf[kt][2], kf[kt][3]);
            }
        }

        // ---- online softmax: exp2 via ex2.approx.f16x2 ----
        float mx0 = -1e30f, mx1 = -1e30f;
        #pragma unroll
        for (int nt = 0; nt < 8; nt++) {
            mx0 = fmaxf(mx0, fmaxf(sv[nt][0], sv[nt][1]));
            mx1 = fmaxf(mx1, fmaxf(sv[nt][2], sv[nt][3]));
        }
        mx0 = fmaxf(mx0, __shfl_xor_sync(0xffffffffu, mx0, 1));
        mx0 = fmaxf(mx0, __shfl_xor_sync(0xffffffffu, mx0, 2));
        mx1 = fmaxf(mx1, __shfl_xor_sync(0xffffffffu, mx1, 1));
        mx1 = fmaxf(mx1, __shfl_xor_sync(0xffffffffu, mx1, 2));

        const float nm0 = fmaxf(m0, mx0), nm1 = fmaxf(m1, mx1);
        const float corr0 = exp2f(m0 - nm0), corr1 = exp2f(m1 - nm1);

        uint32_t pp[8][2];
        float ls0 = 0.0f, ls1 = 0.0f;
        #pragma unroll
        for (int nt = 0; nt < 8; nt++) {
            __half2 a0 = __floats2half2_rn(sv[nt][0] - nm0, sv[nt][1] - nm0);
            __half2 a1 = __floats2half2_rn(sv[nt][2] - nm1, sv[nt][3] - nm1);
            pp[nt][0] = h2ex2(*reinterpret_cast<uint32_t*>(&a0));
            pp[nt][1] = h2ex2(*reinterpret_cast<uint32_t*>(&a1));
            const float2 f0 = __half22float2(*reinterpret_cast<__half2*>(&pp[nt][0]));
            const float2 f1 = __half22float2(*reinterpret_cast<__half2*>(&pp[nt][1]));
            ls0 += f0.x + f0.y;
            ls1 += f1.x + f1.y;
        }
        ls0 += __shfl_xor_sync(0xffffffffu, ls0, 1);
        ls0 += __shfl_xor_sync(0xffffffffu, ls0, 2);
        ls1 += __shfl_xor_sync(0xffffffffu, ls1, 1);
        ls1 += __shfl_xor_sync(0xffffffffu, ls1, 2);
        l0 = l0 * corr0 + ls0; m0 = nm0;
        l1 = l1 * corr1 + ls1; m1 = nm1;
        #pragma unroll
        for (int nt = 0; nt < 8; nt++) {
            oacc[nt][0] *= corr0; oacc[nt][1] *= corr0;
            oacc[nt][2] *= corr1; oacc[nt][3] *= corr1;
        }

        // ---- O += P @ V (frag loads batched per np) ----
        #pragma unroll
        for (int np = 0; np < 4; np++) {
            uint32_t vf[4][4];
            #pragma unroll
            for (int kt = 0; kt < 4; kt++)
                ldsm4(vf[kt], sV + ((np * 16 + lrow) * AKP + kt * 16 + lcol) * 2);
            #pragma unroll
            for (int kt = 0; kt < 4; kt++) {
                const uint32_t ph[4] = {
                    pp[2*kt][0], pp[2*kt][1], pp[2*kt+1][0], pp[2*kt+1][1] };
                mma_f16(oacc[2*np],   ph, vf[kt][0], vf[kt][1]);
                mma_f16(oacc[2*np+1], ph, vf[kt][2], vf[kt][3]);
            }
        }
    }

    // ---- epilogue: normalize, store fp16 hi to [b,s,h*64+d] ----
    const float inv0 = 1.0f / l0, inv1 = 1.0f / l1;
    const int s0 = qt * 128 + wr0 + g;
    const size_t ob0 = ((size_t)b * SEQ + s0) * HID + h * HD;
    const size_t ob1 = ((size_t)b * SEQ + s0 + 8) * HID + h * HD;
    #pragma unroll
    for (int nt = 0; nt < 8; nt++) {
        const int d = nt * 8 + 2 * c;
        *reinterpret_cast<uint32_t*>(Oh + ob0 + d) =
            pack2h(oacc[nt][0] * inv0, oacc[nt][1] * inv0);
        *reinterpret_cast<uint32_t*>(Oh + ob1 + d) =
            pack2h(oacc[nt][2] * inv1, oacc[nt][3] * inv1);
    }
}

// ---------------------------------------------------------------------------
extern "C" void kernel_launch(void* const* d_in, const int* in_sizes, int n_in,
                              void* d_out, int out_size)
{
    const float* X  = (const float*)d_in[0];
    const float* Wq = (const float*)d_in[1];
    const float* bq = (const float*)d_in[2];
    const float* Wk = (const float*)d_in[3];
    const float* bk = (const float*)d_in[4];
    const float* Wv = (const float*)d_in[5];
    const float* bv = (const float*)d_in[6];
    const float* Wo = (const float*)d_in[7];
    const float* bo = (const float*)d_in[8];
    float* out = (float*)d_out;

    fp16 *xh, *wch, *woh, *qh, *kh, *vh, *oh;
    cudaGetSymbolAddress((void**)&xh,  g_xh);
    cudaGetSymbolAddress((void**)&wch, g_wch); cudaGetSymbolAddress((void**)&woh, g_woh);
    cudaGetSymbolAddress((void**)&qh,  g_qh);
    cudaGetSymbolAddress((void**)&kh,  g_kh);  cudaGetSymbolAddress((void**)&vh,  g_vh);
    cudaGetSymbolAddress((void**)&oh,  g_oh);

    cudaFuncSetAttribute(gemm_kernel<0>, cudaFuncAttributeMaxDynamicSharedMemorySize, GEMM_SMEM);
    cudaFuncSetAttribute(gemm_kernel<4>, cudaFuncAttributeMaxDynamicSharedMemorySize, GEMM_SMEM);
    cudaFuncSetAttribute(attn_kernel, cudaFuncAttributeMaxDynamicSharedMemorySize, ATTN_SMEM);

    // ---- single fused convert ----
    convert_all_kernel<<<(ALLF4 + 255) / 256, 256>>>(
        X, Wq, Wk, Wv, Wo, xh, wch, woh);

    dim3 blk(256);
    // Fused QKV projection (1-term): [4096,2048] @ [2048,3072]
    gemm_kernel<4><<<dim3(NC / 128, MTOT / 128), blk, GEMM_SMEM>>>(
        xh, wch, bq, bk, bv, nullptr, MTOT, NC, HID);
    // Attention -> fp16 hi [b,s,h*d]
    attn_kernel<<<dim3(SEQ / 128, NH, BATCH), blk, ATTN_SMEM>>>(
        qh, kh, vh, oh);
    // Output projection (1-term) -> fp32 d_out
    gemm_kernel<0><<<dim3(HID / 128, MTOT / 128), blk, GEMM_SMEM>>>(
        oh, woh, bo, nullptr, nullptr, out, MTOT, HID, HID);
}

// round 16
// speedup vs baseline: 1.2722x; 1.0218x over previous
#include <cuda_runtime.h>
#include <cuda_fp16.h>
#include <cstdint>

#define BATCH 2
#define SEQ   2048
#define HID   2048
#define NH    32
#define NG    8
#define HD    64
#define KVD   (NG*HD)     // 512
#define MTOT  (BATCH*SEQ) // 4096
#define NC    (HID + 2*KVD)  // 3072 combined QKV cols

typedef __half fp16;

// ---------------- device scratch (no allocation allowed) ----------------
__device__ fp16 g_xh[(size_t)MTOT*HID];                           // hi only
__device__ fp16 g_wch[(size_t)HID*NC];                            // [K, Q|K|V] hi only
__device__ fp16 g_woh[(size_t)HID*HID];                           // [K,N] hi only
__device__ fp16 g_qh[(size_t)BATCH*NH*SEQ*HD];                    // hi only
__device__ fp16 g_kh[(size_t)BATCH*NG*SEQ*HD];                    // hi only
__device__ fp16 g_vh[(size_t)BATCH*NG*HD*SEQ];                    // [b,g,d,s] hi only
__device__ fp16 g_oh[(size_t)MTOT*HID];                           // hi only

// ---------------- helpers ----------------
__device__ __forceinline__ uint32_t pack2h(float x0, float x1) {
    __half2 hb = __floats2half2_rn(x0, x1);
    return *reinterpret_cast<uint32_t*>(&hb);
}

__device__ __forceinline__ void mma_f16(float d[4], const uint32_t a[4],
                                        uint32_t b0, uint32_t b1) {
    asm volatile(
        "mma.sync.aligned.m16n8k16.row.col.f32.f16.f16.f32 "
        "{%0,%1,%2,%3}, {%4,%5,%6,%7}, {%8,%9}, {%0,%1,%2,%3};\n"
        : "+f"(d[0]), "+f"(d[1]), "+f"(d[2]), "+f"(d[3])
        : "r"(a[0]), "r"(a[1]), "r"(a[2]), "r"(a[3]), "r"(b0), "r"(b1));
}

__device__ __forceinline__ void ldsm4(uint32_t* r, uint32_t addr) {
    asm volatile("ldmatrix.sync.aligned.m8n8.x4.shared.b16 {%0,%1,%2,%3}, [%4];"
                 : "=r"(r[0]), "=r"(r[1]), "=r"(r[2]), "=r"(r[3]) : "r"(addr));
}
__device__ __forceinline__ void ldsm4t(uint32_t* r, uint32_t addr) {
    asm volatile("ldmatrix.sync.aligned.m8n8.x4.trans.shared.b16 {%0,%1,%2,%3}, [%4];"
                 : "=r"(r[0]), "=r"(r[1]), "=r"(r[2]), "=r"(r[3]) : "r"(addr));
}

__device__ __forceinline__ void cp16(uint32_t saddr, const void* gaddr) {
    asm volatile("cp.async.cg.shared.global [%0], [%1], 16;"
                 :: "r"(saddr), "l"(gaddr) : "memory");
}
#define CP_COMMIT() asm volatile("cp.async.commit_group;" ::: "memory")
#define CP_WAIT2()  asm volatile("cp.async.wait_group 2;"  ::: "memory")

// exp2 on a packed half2 (one MUFU op for two values)
__device__ __forceinline__ uint32_t h2ex2(uint32_t x) {
    uint32_t r;
    asm("ex2.approx.f16x2 %0, %1;" : "=r"(r) : "r"(x));
    return r;
}

// ---------------- fused fp32 -> fp16 convert (X, Wq|Wk|Wv combined, Wo) ---
#define XF4  ((MTOT*HID)/4)       // 2097152
#define WQF4 ((HID*HID)/4)        // 1048576
#define WKF4 ((HID*KVD)/4)        // 262144
#define ALLF4 (XF4 + WQF4 + 2*WKF4 + WQF4)

__global__ __launch_bounds__(256) void convert_all_kernel(
    const float* __restrict__ X,  const float* __restrict__ Wq,
    const float* __restrict__ Wk, const float* __restrict__ Wv,
    const float* __restrict__ Wo,
    fp16* __restrict__ xh, fp16* __restrict__ wch, fp16* __restrict__ woh)
{
    const int i = blockIdx.x * blockDim.x + threadIdx.x;
    if (i >= ALLF4) return;

    if (i < XF4) {
        float4 v = reinterpret_cast<const float4*>(X)[i];
        reinterpret_cast<uint32_t*>(xh)[i * 2]     = pack2h(v.x, v.y);
        reinterpret_cast<uint32_t*>(xh)[i * 2 + 1] = pack2h(v.z, v.w);
        return;
    }
    int j = i - XF4;
    const float* src;
    int Nsrc, colOff;
    if (j < WQF4)                { src = Wq; Nsrc = HID; colOff = 0; }
    else if (j < WQF4 + WKF4)    { src = Wk; Nsrc = KVD; colOff = HID;       j -= WQF4; }
    else if (j < WQF4 + 2*WKF4)  { src = Wv; Nsrc = KVD; colOff = HID + KVD; j -= WQF4 + WKF4; }
    else {                       // Wo -> woh linear
        j -= WQF4 + 2 * WKF4;
        float4 v = reinterpret_cast<const float4*>(Wo)[j];
        reinterpret_cast<uint32_t*>(woh)[j * 2]     = pack2h(v.x, v.y);
        reinterpret_cast<uint32_t*>(woh)[j * 2 + 1] = pack2h(v.z, v.w);
        return;
    }
    const int perRow = Nsrc >> 2;
    const int k = j / perRow;
    const int c4 = (j - k * perRow) * 4;
    float4 v = reinterpret_cast<const float4*>(src)[j];
    const size_t o = ((size_t)k * NC + colOff + c4) >> 1;
    reinterpret_cast<uint32_t*>(wch)[o]     = pack2h(v.x, v.y);
    reinterpret_cast<uint32_t*>(wch)[o + 1] = pack2h(v.z, v.w);
}

// ---------------------------------------------------------------------------
// 1-term fp16 GEMM: CTA 128x128, BK=32, 256 threads (8 warps 4x2, warp tile
// 32x64). 4-stage cp.async pipeline (prefetch distance 3 covers L2 latency),
// wait_group 2 with unconditional commits for exact group accounting.
// MODE 0: fp32 +bias -> Cf (O projection)
// MODE 4: combined QKV epilogue: Q/K/V scatter (K scaled 0.125*log2e)
// ---------------------------------------------------------------------------
#define GAP 40     // A smem pitch (fp16): 32 k + 8 pad
#define GBP 136    // B smem pitch (fp16): 128 n + 8 pad
#define GA_BYTES (128 * GAP * 2)            // 10240
#define GB_BYTES (32 * GBP * 2)             // 8704
#define GSTAGE   (GA_BYTES + GB_BYTES)      // 18944
#define GEMM_SMEM (4 * GSTAGE)              // 75776
#define KSCALE (0.125f * 1.44269504088896f)

template<int MODE>
__global__ __launch_bounds__(256, 2) void gemm_kernel(
    const fp16* __restrict__ Ah, const fp16* __restrict__ Bh,
    const float* __restrict__ bias0, const float* __restrict__ bias1,
    const float* __restrict__ bias2,
    float* __restrict__ Cf, int M, int N, int K)
{
    extern __shared__ char smc[];
    const uint32_t sbase = (uint32_t)__cvta_generic_to_shared(smc);

    const int tid  = threadIdx.x;
    const int lane = tid & 31;
    const int wid  = tid >> 5;
    const int g = lane >> 2, c = lane & 3;
    const int quad = lane >> 3, r8 = lane & 7;
    const int wm0 = (wid & 3) * 32;
    const int wn0 = (wid >> 2) * 64;
    const int row0 = blockIdx.y * 128;
    const int col0 = blockIdx.x * 128;

    float acc[2][8][4];
    #pragma unroll
    for (int mt = 0; mt < 2; mt++)
        #pragma unroll
        for (int nt = 0; nt < 8; nt++)
            #pragma unroll
            for (int j = 0; j < 4; j++) acc[mt][nt][j] = 0.0f;

    const int NT = K / 32;

    auto fill = [&](int kt, int st) {
        const int k0 = kt * 32;
        const uint32_t s0 = sbase + st * GSTAGE;
        #pragma unroll
        for (int i = 0; i < 2; i++) {
            const int idx = tid + i * 256;
            const int r = idx >> 2, q = (idx & 3) * 8;
            const size_t go = (size_t)(row0 + r) * K + k0 + q;
            cp16(s0 + (r * GAP + q) * 2, Ah + go);
        }
        #pragma unroll
        for (int i = 0; i < 2; i++) {
            const int idx = tid + i * 256;
            const int r = idx >> 4, q = (idx & 15) * 8;
            const size_t go = (size_t)(k0 + r) * N + col0 + q;
            cp16(s0 + GA_BYTES + (r * GBP + q) * 2, Bh + go);
        }
    };

    // prefill 3 stages
    fill(0, 0); CP_COMMIT();
    fill(1, 1); CP_COMMIT();
    fill(2, 2); CP_COMMIT();

    const int arow = (quad & 1) * 8 + r8;
    const int acol = (quad >> 1) * 8;

    for (int kt = 0; kt < NT; kt++) {
        CP_WAIT2();                 // retire the group containing fill(kt)
        __syncthreads();
        if (kt + 3 < NT) fill(kt + 3, (kt + 3) & 3);
        CP_COMMIT();                // unconditional (empty groups in tail)
        const uint32_t s0 = sbase + (kt & 3) * GSTAGE;

        #pragma unroll
        for (int kk = 0; kk < 2; kk++) {
            uint32_t ah[2][4], bf[4][4];
            #pragma unroll
            for (int mt = 0; mt < 2; mt++) {
                const uint32_t aaddr =
                    s0 + ((wm0 + mt * 16 + arow) * GAP + kk * 16 + acol) * 2;
                ldsm4(ah[mt], aaddr);
            }
            #pragma unroll
            for (int np = 0; np < 4; np++) {
                const uint32_t baddr = s0 + GA_BYTES +
                    ((kk * 16 + arow) * GBP + wn0 + np * 16 + acol) * 2;
                ldsm4t(bf[np], baddr);
            }
            #pragma unroll
            for (int np = 0; np < 4; np++)
                #pragma unroll
                for (int mt = 0; mt < 2; mt++) {
                    mma_f16(acc[mt][2*np],   ah[mt], bf[np][0], bf[np][1]);
                    mma_f16(acc[mt][2*np+1], ah[mt], bf[np][2], bf[np][3]);
                }
        }
    }

    // ---- epilogue ----
    #pragma unroll
    for (int mt = 0; mt < 2; mt++) {
        const int r = row0 + wm0 + mt * 16 + g;     // and r+8
        const int b0 = r >> 11, s0i = r & 2047;
        const int b1 = (r + 8) >> 11, s1i = (r + 8) & 2047;
        #pragma unroll
        for (int nt = 0; nt < 8; nt++) {
            const int n = col0 + wn0 + nt * 8 + 2 * c;
            if (MODE == 0) {
                const float bv0 = bias0[n], bv1 = bias0[n + 1];
                const float v0 = acc[mt][nt][0] + bv0;
                const float v1 = acc[mt][nt][1] + bv1;
                const float v2 = acc[mt][nt][2] + bv0;
                const float v3 = acc[mt][nt][3] + bv1;
                *(float2*)(Cf + (size_t)r * N + n)       = make_float2(v0, v1);
                *(float2*)(Cf + (size_t)(r + 8) * N + n) = make_float2(v2, v3);
            } else {
                if (n < HID) {               // ---- Q: hi [b,h,s,d] ----
                    const float bv0 = bias0[n], bv1 = bias0[n + 1];
                    const int hh = n >> 6, d = n & 63;
                    size_t o0 = (((size_t)(b0 * NH + hh)) * SEQ + s0i) * HD + d;
                    size_t o1 = (((size_t)(b1 * NH + hh)) * SEQ + s1i) * HD + d;
                    *reinterpret_cast<uint32_t*>(g_qh + o0) =
                        pack2h(acc[mt][nt][0] + bv0, acc[mt][nt][1] + bv1);
                    *reinterpret_cast<uint32_t*>(g_qh + o1) =
                        pack2h(acc[mt][nt][2] + bv0, acc[mt][nt][3] + bv1);
                } else if (n < HID + KVD) {  // ---- K: hi [b,g,s,d], xKSCALE ----
                    const int nn = n - HID;
                    const float bv0 = bias1[nn], bv1 = bias1[nn + 1];
                    const float v0 = (acc[mt][nt][0] + bv0) * KSCALE;
                    const float v1 = (acc[mt][nt][1] + bv1) * KSCALE;
                    const float v2 = (acc[mt][nt][2] + bv0) * KSCALE;
                    const float v3 = (acc[mt][nt][3] + bv1) * KSCALE;
                    const int gg = nn >> 6, d = nn & 63;
                    size_t o0 = (((size_t)(b0 * NG + gg)) * SEQ + s0i) * HD + d;
                    size_t o1 = (((size_t)(b1 * NG + gg)) * SEQ + s1i) * HD + d;
                    *reinterpret_cast<uint32_t*>(g_kh + o0) = pack2h(v0, v1);
                    *reinterpret_cast<uint32_t*>(g_kh + o1) = pack2h(v2, v3);
                } else {                     // ---- V: hi transposed [b,g,d,s] ----
                    const int nn = n - HID - KVD;
                    const float bv0 = bias2[nn], bv1 = bias2[nn + 1];
                    const float vals[4] = {
                        acc[mt][nt][0] + bv0, acc[mt][nt][1] + bv1,
                        acc[mt][nt][2] + bv0, acc[mt][nt][3] + bv1 };
                    const int gg = nn >> 6, d = nn & 63;
                    const size_t base0 = ((size_t)(b0 * NG + gg)) * HD;
                    const size_t base1 = ((size_t)(b1 * NG + gg)) * HD;
                    const size_t offs[4] = {
                        (base0 + d) * SEQ + s0i, (base0 + d + 1) * SEQ + s0i,
                        (base1 + d) * SEQ + s1i, (base1 + d + 1) * SEQ + s1i };
                    #pragma unroll
                    for (int j = 0; j < 4; j++)
                        g_vh[offs[j]] = __float2half_rn(vals[j]);
                }
            }
        }
    }
}

// ---------------------------------------------------------------------------
// Flash attention: 1-term fp16 QK + 1-term PV, K/V hi-only in smem,
// ex2.approx.f16x2 softmax, 4-stage cp.async pipeline (distance 3).
// Block = (b, h, 128-query tile), 256 threads.
// ---------------------------------------------------------------------------
#define AKP 72
#define AK_BYTES (64 * AKP * 2)        // 9216
#define ASTAGE   (2 * AK_BYTES)        // 18432
#define ATTN_SMEM (4 * ASTAGE)         // 73728
#define NTL (SEQ / 64)                 // 32 key tiles

__global__ __launch_bounds__(256, 2) void attn_kernel(
    const fp16* __restrict__ Qh, const fp16* __restrict__ Kh,
    const fp16* __restrict__ Vh, fp16* __restrict__ Oh)
{
    extern __shared__ char smc[];
    const uint32_t sbase = (uint32_t)__cvta_generic_to_shared(smc);

    const int tid  = threadIdx.x;
    const int lane = tid & 31;
    const int wid  = tid >> 5;
    const int g = lane >> 2, c = lane & 3;
    const int quad = lane >> 3, r8 = lane & 7;
    const int wr0 = wid * 16;
    const int lrow = (quad >> 1) * 8 + r8;
    const int lcol = (quad & 1) * 8;

    const int qt = blockIdx.x;
    const int h  = blockIdx.y;
    const int b  = blockIdx.z;
    const int gh = h >> 2;

    const size_t koff = ((size_t)(b * NG + gh)) * SEQ * HD;
    const size_t voff = ((size_t)(b * NG + gh)) * HD * SEQ;

    const fp16* qbh = Qh + (((size_t)(b * NH + h)) * SEQ + qt * 128 + wr0) * HD;
    uint32_t qh[4][4];
    #pragma unroll
    for (int kt = 0; kt < 4; kt++) {
        const int o0 = g * HD + kt * 16 + 2 * c;
        qh[kt][0] = *(const uint32_t*)(qbh + o0);
        qh[kt][1] = *(const uint32_t*)(qbh + o0 + 8 * HD);
        qh[kt][2] = *(const uint32_t*)(qbh + o0 + 8);
        qh[kt][3] = *(const uint32_t*)(qbh + o0 + 8 * HD + 8);
    }

    auto fill = [&](int t, int st) {
        const uint32_t s0 = sbase + st * ASTAGE;
        #pragma unroll
        for (int i = 0; i < 2; i++) {
            const int idx = tid + i * 256;
            const int r = idx >> 3, q = (idx & 7) * 8;
            const uint32_t so = (r * AKP + q) * 2;
            const size_t gk = koff + (size_t)(t * 64 + r) * HD + q;
            cp16(s0 + so, Kh + gk);
            const size_t gv = voff + (size_t)r * SEQ + t * 64 + q;
            cp16(s0 + AK_BYTES + so, Vh + gv);
        }
    };

    float m0 = -1e30f, m1 = -1e30f, l0 = 0.0f, l1 = 0.0f;
    float oacc[8][4];
    #pragma unroll
    for (int nt = 0; nt < 8; nt++)
        #pragma unroll
        for (int j = 0; j < 4; j++) oacc[nt][j] = 0.0f;

    // prefill 3 stages
    fill(0, 0); CP_COMMIT();
    fill(1, 1); CP_COMMIT();
    fill(2, 2); CP_COMMIT();

    for (int t = 0; t < NTL; t++) {
        CP_WAIT2();
        __syncthreads();
        if (t + 3 < NTL) fill(t + 3, (t + 3) & 3);
        CP_COMMIT();
        const uint32_t sK = sbase + (t & 3) * ASTAGE;
        const uint32_t sV = sK + AK_BYTES;

        // ---- S = Q @ K^T ----
        float sv[8][4];
        #pragma unroll
        for (int nt = 0; nt < 8; nt++)
            #pragma unroll
            for (int j = 0; j < 4; j++) sv[nt][j] = 0.0f;

        #pragma unroll
        for (int np = 0; np < 4; np++) {
            uint32_t kf[4][4];
            #pragma unroll
            for (int kt = 0; kt < 4; kt++)
                ldsm4(kf[kt], sK + ((np * 16 + lrow) * AKP + kt * 16 + lcol) * 2);
            #pragma unroll
            for (int kt = 0; kt < 4; kt++) {
                mma_f16(sv[2*np],   qh[kt], kf[kt][0], kf[kt][1]);
                mma_f16(sv[2*np+1], qh[kt], kf[kt][2], kf[kt][3]);
            }
        }

        // ---- online softmax: exp2 via ex2.approx.f16x2 ----
        float mx0 = -1e30f, mx1 = -1e30f;
        #pragma unroll
        for (int nt = 0; nt < 8; nt++) {
            mx0 = fmaxf(mx0, fmaxf(sv[nt][0], sv[nt][1]));
            mx1 = fmaxf(mx1, fmaxf(sv[nt][2], sv[nt][3]));
        }
        mx0 = fmaxf(mx0, __shfl_xor_sync(0xffffffffu, mx0, 1));
        mx0 = fmaxf(mx0, __shfl_xor_sync(0xffffffffu, mx0, 2));
        mx1 = fmaxf(mx1, __shfl_xor_sync(0xffffffffu, mx1, 1));
        mx1 = fmaxf(mx1, __shfl_xor_sync(0xffffffffu, mx1, 2));

        const float nm0 = fmaxf(m0, mx0), nm1 = fmaxf(m1, mx1);
        const float corr0 = exp2f(m0 - nm0), corr1 = exp2f(m1 - nm1);

        uint32_t pp[8][2];
        float ls0 = 0.0f, ls1 = 0.0f;
        #pragma unroll
        for (int nt = 0; nt < 8; nt++) {
            __half2 a0 = __floats2half2_rn(sv[nt][0] - nm0, sv[nt][1] - nm0);
            __half2 a1 = __floats2half2_rn(sv[nt][2] - nm1, sv[nt][3] - nm1);
            pp[nt][0] = h2ex2(*reinterpret_cast<uint32_t*>(&a0));
            pp[nt][1] = h2ex2(*reinterpret_cast<uint32_t*>(&a1));
            const float2 f0 = __half22float2(*reinterpret_cast<__half2*>(&pp[nt][0]));
            const float2 f1 = __half22float2(*reinterpret_cast<__half2*>(&pp[nt][1]));
            ls0 += f0.x + f0.y;
            ls1 += f1.x + f1.y;
        }
        ls0 += __shfl_xor_sync(0xffffffffu, ls0, 1);
        ls0 += __shfl_xor_sync(0xffffffffu, ls0, 2);
        ls1 += __shfl_xor_sync(0xffffffffu, ls1, 1);
        ls1 += __shfl_xor_sync(0xffffffffu, ls1, 2);
        l0 = l0 * corr0 + ls0; m0 = nm0;
        l1 = l1 * corr1 + ls1; m1 = nm1;
        #pragma unroll
        for (int nt = 0; nt < 8; nt++) {
            oacc[nt][0] *= corr0; oacc[nt][1] *= corr0;
            oacc[nt][2] *= corr1; oacc[nt][3] *= corr1;
        }

        // ---- O += P @ V ----
        #pragma unroll
        for (int np = 0; np < 4; np++) {
            uint32_t vf[4][4];
            #pragma unroll
            for (int kt = 0; kt < 4; kt++)
                ldsm4(vf[kt], sV + ((np * 16 + lrow) * AKP + kt * 16 + lcol) * 2);
            #pragma unroll
            for (int kt = 0; kt < 4; kt++) {
                const uint32_t ph[4] = {
                    pp[2*kt][0], pp[2*kt][1], pp[2*kt+1][0], pp[2*kt+1][1] };
                mma_f16(oacc[2*np],   ph, vf[kt][0], vf[kt][1]);
                mma_f16(oacc[2*np+1], ph, vf[kt][2], vf[kt][3]);
            }
        }
    }

    // ---- epilogue: normalize, store fp16 hi to [b,s,h*64+d] ----
    const float inv0 = 1.0f / l0, inv1 = 1.0f / l1;
    const int s0 = qt * 128 + wr0 + g;
    const size_t ob0 = ((size_t)b * SEQ + s0) * HID + h * HD;
    const size_t ob1 = ((size_t)b * SEQ + s0 + 8) * HID + h * HD;
    #pragma unroll
    for (int nt = 0; nt < 8; nt++) {
        const int d = nt * 8 + 2 * c;
        *reinterpret_cast<uint32_t*>(Oh + ob0 + d) =
            pack2h(oacc[nt][0] * inv0, oacc[nt][1] * inv0);
        *reinterpret_cast<uint32_t*>(Oh + ob1 + d) =
            pack2h(oacc[nt][2] * inv1, oacc[nt][3] * inv1);
    }
}

// ---------------------------------------------------------------------------
extern "C" void kernel_launch(void* const* d_in, const int* in_sizes, int n_in,
                              void* d_out, int out_size)
{
    const float* X  = (const float*)d_in[0];
    const float* Wq = (const float*)d_in[1];
    const float* bq = (const float*)d_in[2];
    const float* Wk = (const float*)d_in[3];
    const float* bk = (const float*)d_in[4];
    const float* Wv = (const float*)d_in[5];
    const float* bv = (const float*)d_in[6];
    const float* Wo = (const float*)d_in[7];
    const float* bo = (const float*)d_in[8];
    float* out = (float*)d_out;

    fp16 *xh, *wch, *woh, *qh, *kh, *vh, *oh;
    cudaGetSymbolAddress((void**)&xh,  g_xh);
    cudaGetSymbolAddress((void**)&wch, g_wch); cudaGetSymbolAddress((void**)&woh, g_woh);
    cudaGetSymbolAddress((void**)&qh,  g_qh);
    cudaGetSymbolAddress((void**)&kh,  g_kh);  cudaGetSymbolAddress((void**)&vh,  g_vh);
    cudaGetSymbolAddress((void**)&oh,  g_oh);

    cudaFuncSetAttribute(gemm_kernel<0>, cudaFuncAttributeMaxDynamicSharedMemorySize, GEMM_SMEM);
    cudaFuncSetAttribute(gemm_kernel<4>, cudaFuncAttributeMaxDynamicSharedMemorySize, GEMM_SMEM);
    cudaFuncSetAttribute(attn_kernel, cudaFuncAttributeMaxDynamicSharedMemorySize, ATTN_SMEM);

    // ---- single fused convert ----
    convert_all_kernel<<<(ALLF4 + 255) / 256, 256>>>(
        X, Wq, Wk, Wv, Wo, xh, wch, woh);

    dim3 blk(256);
    // Fused QKV projection (1-term): [4096,2048] @ [2048,3072]
    gemm_kernel<4><<<dim3(NC / 128, MTOT / 128), blk, GEMM_SMEM>>>(
        xh, wch, bq, bk, bv, nullptr, MTOT, NC, HID);
    // Attention -> fp16 hi [b,s,h*d]
    attn_kernel<<<dim3(SEQ / 128, NH, BATCH), blk, ATTN_SMEM>>>(
        qh, kh, vh, oh);
    // Output projection (1-term) -> fp32 d_out
    gemm_kernel<0><<<dim3(HID / 128, MTOT / 128), blk, GEMM_SMEM>>>(
        oh, woh, bo, nullptr, nullptr, out, MTOT, HID, HID);
}